// round 15
// baseline (speedup 1.0000x reference)
#include <cuda_runtime.h>
#include <cuda_fp16.h>
#include <cstdint>
#include <math.h>

// ---------------- problem constants ----------------
#define B_  64
#define T_  512
#define H_  1024
#define U_  1024
#define M_  (B_ * T_)          // 32768
#define NBLK 8                 // U_/128 column blocks

// ---------------- GEMM tiling: 4 warps, 64x64 warp tiles ----------------
#define BM 128
#define BN 128
#define KSTEP 16
#define NK (H_ / KSTEP)        // 64 k-steps
#define TILEB 4096             // 128 rows * 32B (swizzled)
#define STAGEB (2 * TILEB)     // Ah, Bh = 8 KB per stage
#define PIPE 4
#define SMEM_TOTAL (PIPE * STAGEB)   // 32768 B

// ---------------- context tiling ----------------
#define TCH 16                 // t-chunks per batch (validated optimum)
#define TSEG (T_ / TCH)        // 32

// ---------------- device scratch ----------------
__device__ __half g_Ah[(size_t)M_ * H_];
__device__ __half g_Bh[(size_t)U_ * H_];   // Wh^T as [n][k], fp16
__device__ float g_partial[(size_t)M_ * NBLK];
__device__ float g_ctxp[(size_t)B_ * TCH * H_];   // context partials

// ---------------- helpers ----------------
__device__ __forceinline__ uint32_t smem_u32(const void* p) {
    uint32_t a;
    asm("{ .reg .u64 t; cvta.to.shared.u64 t, %1; cvt.u32.u64 %0, t; }" : "=r"(a) : "l"(p));
    return a;
}
__device__ __forceinline__ void cp16(uint32_t dst, const void* src) {
    asm volatile("cp.async.cg.shared.global [%0], [%1], 16;" :: "r"(dst), "l"(src));
}
__device__ __forceinline__ void cp_commit() { asm volatile("cp.async.commit_group;" ::: "memory"); }
template <int N_> __device__ __forceinline__ void cp_wait() {
    asm volatile("cp.async.wait_group %0;" :: "n"(N_) : "memory");
}
__device__ __forceinline__ void ldsm4(uint32_t* r, uint32_t a) {
    asm volatile("ldmatrix.sync.aligned.m8n8.x4.shared.b16 {%0,%1,%2,%3}, [%4];"
                 : "=r"(r[0]), "=r"(r[1]), "=r"(r[2]), "=r"(r[3]) : "r"(a));
}
__device__ __forceinline__ void mma16816(float* d, const uint32_t* a, uint32_t b0, uint32_t b1) {
    asm volatile(
        "mma.sync.aligned.m16n8k16.row.col.f32.f16.f16.f32 "
        "{%0,%1,%2,%3},{%4,%5,%6,%7},{%8,%9},{%0,%1,%2,%3};"
        : "+f"(d[0]), "+f"(d[1]), "+f"(d[2]), "+f"(d[3])
        : "r"(a[0]), "r"(a[1]), "r"(a[2]), "r"(a[3]), "r"(b0), "r"(b1));
}
// single-MUFU tanh (sm_75+)
__device__ __forceinline__ float tanh_fast(float x) {
    float y;
    asm("tanh.approx.f32 %0, %1;" : "=f"(y) : "f"(x));
    return y;
}
// 16B-chunk swizzle within a [128 x 32B] tile (verified conflict-free).
__device__ __forceinline__ uint32_t tile_off(int row, int c) {
    const int r8  = row & 7;
    const int idx = r8 * 2 + (c ^ ((r8 >> 2) & 1));
    return (uint32_t)((row >> 3) * 256 + idx * 16);
}

// ---------------------------------------------------------------------------
// Kernel 0a: convert enc fp32 -> fp16, 16 elems/thread
// ---------------------------------------------------------------------------
__global__ __launch_bounds__(256)
void k_convA(const float* __restrict__ A)
{
    size_t i = ((size_t)blockIdx.x * 256 + threadIdx.x) * 16;
    float4 v0 = *(const float4*)(A + i);
    float4 v1 = *(const float4*)(A + i + 4);
    float4 v2 = *(const float4*)(A + i + 8);
    float4 v3 = *(const float4*)(A + i + 12);
    __half2 h0 = __floats2half2_rn(v0.x, v0.y);
    __half2 h1 = __floats2half2_rn(v0.z, v0.w);
    __half2 h2 = __floats2half2_rn(v1.x, v1.y);
    __half2 h3 = __floats2half2_rn(v1.z, v1.w);
    __half2 h4 = __floats2half2_rn(v2.x, v2.y);
    __half2 h5 = __floats2half2_rn(v2.z, v2.w);
    __half2 h6 = __floats2half2_rn(v3.x, v3.y);
    __half2 h7 = __floats2half2_rn(v3.z, v3.w);
    uint4 o0, o1;
    o0.x = *(const uint32_t*)&h0; o0.y = *(const uint32_t*)&h1;
    o0.z = *(const uint32_t*)&h2; o0.w = *(const uint32_t*)&h3;
    o1.x = *(const uint32_t*)&h4; o1.y = *(const uint32_t*)&h5;
    o1.z = *(const uint32_t*)&h6; o1.w = *(const uint32_t*)&h7;
    *(uint4*)(g_Ah + i)     = o0;
    *(uint4*)(g_Ah + i + 8) = o1;
}

// ---------------------------------------------------------------------------
// Kernel 0b: transpose Wh [K,N] fp32 -> g_Bh [N,K] fp16
// ---------------------------------------------------------------------------
__global__ __launch_bounds__(256)
void k_convB(const float* __restrict__ Wh)
{
    __shared__ float tile[32][33];
    const int k0 = blockIdx.y * 32, n0 = blockIdx.x * 32;
    const int tx = threadIdx.x, ty = threadIdx.y;   // 32 x 8
#pragma unroll
    for (int r = 0; r < 4; r++)
        tile[ty + r * 8][tx] = Wh[(size_t)(k0 + ty + r * 8) * U_ + n0 + tx];
    __syncthreads();
#pragma unroll
    for (int r = 0; r < 4; r++) {
        int n = n0 + ty + r * 8;
        int k = k0 + tx;
        g_Bh[(size_t)n * H_ + k] = __float2half(tile[tx][ty + r * 8]);
    }
}

// ---------------------------------------------------------------------------
// Kernel 1: fp16 GEMM, 4 warps x (64x64) warp tiles -- 33% less smem read
// traffic than the 8-warp 32x64 layout. Same swizzle/pipeline skeleton.
// ---------------------------------------------------------------------------
__global__ __launch_bounds__(128, 2)
void k_gemm_mma(const float* __restrict__ bh, const float* __restrict__ Wv)
{
    extern __shared__ char smem[];
    const uint32_t sb = smem_u32(smem);

    const int tid  = threadIdx.x;
    const int warp = tid >> 5;
    const int lane = tid & 31;
    const int g    = lane >> 2;
    const int tig  = lane & 3;
    const int warpM = warp >> 1;      // 0..1  (64-row slab)
    const int warpN = warp & 1;       // 0..1  (64-col slab)

    const int rowBase = blockIdx.y * BM;
    const int colBase = blockIdx.x * BN;

    // cp.async: thread tid owns row tid of both tiles (2 chunks each)
    const size_t gRowA = (size_t)(rowBase + tid) * H_;
    const size_t gRowB = (size_t)(colBase + tid) * H_;
    const uint32_t sA0 = tile_off(tid, 0);
    const uint32_t sA1 = tile_off(tid, 1);

#define LOAD_STAGE(KT, BUF)                                                    \
    do {                                                                       \
        const uint32_t base_ = sb + (BUF) * STAGEB;                            \
        const size_t kk_ = (size_t)(KT) * KSTEP;                               \
        cp16(base_ + sA0, g_Ah + gRowA + kk_);                                 \
        cp16(base_ + sA1, g_Ah + gRowA + kk_ + 8);                             \
        cp16(base_ + TILEB + sA0, g_Bh + gRowB + kk_);                         \
        cp16(base_ + TILEB + sA1, g_Bh + gRowB + kk_ + 8);                     \
        cp_commit();                                                           \
    } while (0)

    // ldmatrix per-lane offsets
    const int sub = lane >> 3, q = lane & 7;
    uint32_t aOff[4];
#pragma unroll
    for (int mi = 0; mi < 4; mi++) {
        const int rowA = warpM * 64 + mi * 16 + ((sub & 1) ? 8 : 0) + q;
        aOff[mi] = tile_off(rowA, sub >> 1);
    }
    uint32_t bOff[4];
#pragma unroll
    for (int nip = 0; nip < 4; nip++) {
        const int rowB = warpN * 64 + nip * 16 + ((sub & 2) ? 8 : 0) + q;
        bOff[nip] = tile_off(rowB, sub & 1);
    }

    float d[4][8][4];
#pragma unroll
    for (int mi = 0; mi < 4; mi++)
#pragma unroll
        for (int ni = 0; ni < 8; ni++)
#pragma unroll
            for (int qq = 0; qq < 4; qq++) d[mi][ni][qq] = 0.0f;

    LOAD_STAGE(0, 0);
    LOAD_STAGE(1, 1);
    LOAD_STAGE(2, 2);

#pragma unroll 2
    for (int kt = 0; kt < NK; kt++) {
        cp_wait<2>();
        __syncthreads();
        if (kt + 3 < NK) LOAD_STAGE(kt + 3, (kt + 3) & (PIPE - 1));
        else cp_commit();

        const uint32_t stage = sb + (uint32_t)(kt & (PIPE - 1)) * STAGEB;
        const uint32_t Ah_s = stage, Bh_s = stage + TILEB;

        uint32_t ah[4][4];
        ldsm4(ah[0], Ah_s + aOff[0]);
        ldsm4(ah[1], Ah_s + aOff[1]);
        ldsm4(ah[2], Ah_s + aOff[2]);
        ldsm4(ah[3], Ah_s + aOff[3]);

#pragma unroll
        for (int nip = 0; nip < 4; nip++) {
            uint32_t b4[4];
            ldsm4(b4, Bh_s + bOff[nip]);
            const int n0 = nip * 2, n1 = n0 + 1;
#pragma unroll
            for (int mi = 0; mi < 4; mi++) {
                mma16816(d[mi][n0], ah[mi], b4[0], b4[1]);
                mma16816(d[mi][n1], ah[mi], b4[2], b4[3]);
            }
        }
    }
    __syncthreads();

    // fused epilogue: s = sum_n tanh(C + bh)*Wv over this warp's 64 cols
    float s[4][2];
#pragma unroll
    for (int mi = 0; mi < 4; mi++) { s[mi][0] = 0.f; s[mi][1] = 0.f; }
#pragma unroll
    for (int ni = 0; ni < 8; ni++) {
        const int n0 = colBase + warpN * 64 + ni * 8 + 2 * tig;
        const float bb0 = __ldg(bh + n0), bb1 = __ldg(bh + n0 + 1);
        const float w0  = __ldg(Wv + n0), w1  = __ldg(Wv + n0 + 1);
#pragma unroll
        for (int mi = 0; mi < 4; mi++) {
            s[mi][0] = fmaf(tanh_fast(d[mi][ni][0] + bb0), w0, s[mi][0]);
            s[mi][0] = fmaf(tanh_fast(d[mi][ni][1] + bb1), w1, s[mi][0]);
            s[mi][1] = fmaf(tanh_fast(d[mi][ni][2] + bb0), w0, s[mi][1]);
            s[mi][1] = fmaf(tanh_fast(d[mi][ni][3] + bb1), w1, s[mi][1]);
        }
    }
#pragma unroll
    for (int off = 1; off <= 2; off <<= 1) {
#pragma unroll
        for (int mi = 0; mi < 4; mi++) {
            s[mi][0] += __shfl_xor_sync(0xFFFFFFFFu, s[mi][0], off);
            s[mi][1] += __shfl_xor_sync(0xFFFFFFFFu, s[mi][1], off);
        }
    }
    float* red = (float*)smem;   // [128][2]
    if (tig == 0) {
#pragma unroll
        for (int mi = 0; mi < 4; mi++) {
            red[(warpM * 64 + mi * 16 + g) * 2 + warpN]     = s[mi][0];
            red[(warpM * 64 + mi * 16 + 8 + g) * 2 + warpN] = s[mi][1];
        }
    }
    __syncthreads();
    g_partial[(size_t)(rowBase + tid) * NBLK + blockIdx.x] = red[tid * 2] + red[tid * 2 + 1];
#undef LOAD_STAGE
}

// ---------------------------------------------------------------------------
// Kernel 2: fused softmax + context partial (reads fp16 g_Ah), TCH=16
// ---------------------------------------------------------------------------
__global__ __launch_bounds__(256)
void k_ctx_fused(float* __restrict__ attn_out)
{
    const int tc  = blockIdx.x;
    const int b   = blockIdx.y;
    const int tid = threadIdx.x;

    __shared__ float w[T_];
    __shared__ float rbuf[8];

    const float* p0 = g_partial + ((size_t)b * T_ + tid) * NBLK;
    const float* p1 = g_partial + ((size_t)b * T_ + tid + 256) * NBLK;
    float s0 = 0.f, s1 = 0.f;
#pragma unroll
    for (int i = 0; i < NBLK; i++) { s0 += p0[i]; s1 += p1[i]; }

    float mx = fmaxf(s0, s1);
#pragma unroll
    for (int o = 16; o > 0; o >>= 1) mx = fmaxf(mx, __shfl_xor_sync(0xFFFFFFFFu, mx, o));
    if ((tid & 31) == 0) rbuf[tid >> 5] = mx;
    __syncthreads();
    mx = rbuf[0];
#pragma unroll
    for (int i = 1; i < 8; i++) mx = fmaxf(mx, rbuf[i]);
    __syncthreads();

    const float e0 = expf(s0 - mx);
    const float e1 = expf(s1 - mx);

    float sm = e0 + e1;
#pragma unroll
    for (int o = 16; o > 0; o >>= 1) sm += __shfl_xor_sync(0xFFFFFFFFu, sm, o);
    if ((tid & 31) == 0) rbuf[tid >> 5] = sm;
    __syncthreads();
    sm = rbuf[0];
#pragma unroll
    for (int i = 1; i < 8; i++) sm += rbuf[i];

    const float inv = __fdividef(1.0f, sm);
    w[tid]       = e0 * inv;
    w[tid + 256] = e1 * inv;
    if (tc == 0) {
        attn_out[b * T_ + tid]       = e0 * inv;
        attn_out[b * T_ + tid + 256] = e1 * inv;
    }
    __syncthreads();

    const int h0 = tid * 4;
    const __half* base = g_Ah + ((size_t)b * T_ + tc * TSEG) * H_ + h0;
    float a0 = 0.f, a1 = 0.f, a2 = 0.f, a3 = 0.f;
#pragma unroll 8
    for (int t = 0; t < TSEG; t++) {
        const float wt = w[tc * TSEG + t];
        const uint2 v = *(const uint2*)(base + (size_t)t * H_);
        const __half2 q0 = *(const __half2*)&v.x;
        const __half2 q1 = *(const __half2*)&v.y;
        const float2 f0 = __half22float2(q0);
        const float2 f1 = __half22float2(q1);
        a0 = fmaf(wt, f0.x, a0);
        a1 = fmaf(wt, f0.y, a1);
        a2 = fmaf(wt, f1.x, a2);
        a3 = fmaf(wt, f1.y, a3);
    }
    float4 r = make_float4(a0, a1, a2, a3);
    *(float4*)(g_ctxp + (size_t)(b * TCH + tc) * H_ + h0) = r;
}

// ---------------------------------------------------------------------------
// Kernel 3: reduce context partials, float4 per thread
// ---------------------------------------------------------------------------
__global__ __launch_bounds__(256)
void k_ctx_reduce(float* __restrict__ ctx)
{
    const int i4 = blockIdx.x * 256 + threadIdx.x;   // over B_*H_/4
    const int b  = (i4 * 4) >> 10;
    const int h  = (i4 * 4) & (H_ - 1);
    float4 s = make_float4(0.f, 0.f, 0.f, 0.f);
#pragma unroll
    for (int p = 0; p < TCH; p++) {
        const float4 v = *(const float4*)(g_ctxp + (size_t)(b * TCH + p) * H_ + h);
        s.x += v.x; s.y += v.y; s.z += v.z; s.w += v.w;
    }
    ((float4*)ctx)[i4] = s;
}

// ---------------------------------------------------------------------------
// Launch. Inputs: dec_hidden, enc_output, Wh, bh, Ws, bs, Wv, bv.
// dec/Ws/bs/bv cancel inside softmax. Output: [ctx (64*1024) | attn (64*512)].
// ---------------------------------------------------------------------------
extern "C" void kernel_launch(void* const* d_in, const int* in_sizes, int n_in,
                              void* d_out, int out_size)
{
    (void)in_sizes; (void)n_in; (void)out_size;
    const float* enc = (const float*)d_in[1];
    const float* Wh  = (const float*)d_in[2];
    const float* bh  = (const float*)d_in[3];
    const float* Wv  = (const float*)d_in[6];

    float* out  = (float*)d_out;
    float* ctx  = out;
    float* attn = out + B_ * H_;

    static bool attr_done = false;
    if (!attr_done) {
        cudaFuncSetAttribute(k_gemm_mma, cudaFuncAttributeMaxDynamicSharedMemorySize, SMEM_TOTAL);
        attr_done = true;
    }

    k_convA<<<(M_ * H_) / (256 * 16), 256>>>(enc);
    k_convB<<<dim3(U_ / 32, H_ / 32), dim3(32, 8)>>>(Wh);
    k_gemm_mma<<<dim3(NBLK, M_ / BM), 128, SMEM_TOTAL>>>(bh, Wv);
    k_ctx_fused<<<dim3(TCH, B_), 256>>>(attn);
    k_ctx_reduce<<<(B_ * H_) / (256 * 4), 256>>>(ctx);
}

// round 16
// speedup vs baseline: 1.4250x; 1.4250x over previous
#include <cuda_runtime.h>
#include <cuda_fp16.h>
#include <cstdint>
#include <math.h>

// ---------------- problem constants ----------------
#define B_  64
#define T_  512
#define H_  1024
#define U_  1024
#define M_  (B_ * T_)          // 32768
#define NBLK 8                 // U_/128 column blocks

// ---------------- GEMM tiling (R14 proven optimum) ----------------
#define BM 128
#define BN 128
#define KSTEP 16
#define NK (H_ / KSTEP)        // 64 k-steps
#define TILEB 4096             // 128 rows * 32B (swizzled)
#define STAGEB (2 * TILEB)     // Ah, Bh = 8 KB per stage
#define PIPE 4
#define SMEM_TOTAL (PIPE * STAGEB)   // 32768 B dynamic

// ---------------- context tiling ----------------
#define TCH 16                 // t-chunks per batch (validated optimum)
#define TSEG (T_ / TCH)        // 32

// ---------------- device scratch ----------------
__device__ __half g_Ah[(size_t)M_ * H_];
__device__ __half g_Bh[(size_t)U_ * H_];   // Wh^T as [n][k], fp16
__device__ float g_partial[(size_t)M_ * NBLK];
__device__ float g_ctxp[(size_t)B_ * TCH * H_];   // context partials

// ---------------- helpers ----------------
__device__ __forceinline__ uint32_t smem_u32(const void* p) {
    uint32_t a;
    asm("{ .reg .u64 t; cvta.to.shared.u64 t, %1; cvt.u32.u64 %0, t; }" : "=r"(a) : "l"(p));
    return a;
}
__device__ __forceinline__ void cp16(uint32_t dst, const void* src) {
    asm volatile("cp.async.cg.shared.global [%0], [%1], 16;" :: "r"(dst), "l"(src));
}
__device__ __forceinline__ void cp_commit() { asm volatile("cp.async.commit_group;" ::: "memory"); }
template <int N_> __device__ __forceinline__ void cp_wait() {
    asm volatile("cp.async.wait_group %0;" :: "n"(N_) : "memory");
}
__device__ __forceinline__ void ldsm4(uint32_t* r, uint32_t a) {
    asm volatile("ldmatrix.sync.aligned.m8n8.x4.shared.b16 {%0,%1,%2,%3}, [%4];"
                 : "=r"(r[0]), "=r"(r[1]), "=r"(r[2]), "=r"(r[3]) : "r"(a));
}
__device__ __forceinline__ void mma16816(float* d, const uint32_t* a, uint32_t b0, uint32_t b1) {
    asm volatile(
        "mma.sync.aligned.m16n8k16.row.col.f32.f16.f16.f32 "
        "{%0,%1,%2,%3},{%4,%5,%6,%7},{%8,%9},{%0,%1,%2,%3};"
        : "+f"(d[0]), "+f"(d[1]), "+f"(d[2]), "+f"(d[3])
        : "r"(a[0]), "r"(a[1]), "r"(a[2]), "r"(a[3]), "r"(b0), "r"(b1));
}
// single-MUFU tanh (sm_75+)
__device__ __forceinline__ float tanh_fast(float x) {
    float y;
    asm("tanh.approx.f32 %0, %1;" : "=f"(y) : "f"(x));
    return y;
}
// 16B-chunk swizzle within a [128 x 32B] tile (verified conflict-free).
__device__ __forceinline__ uint32_t tile_off(int row, int c) {
    const int r8  = row & 7;
    const int idx = r8 * 2 + (c ^ ((r8 >> 2) & 1));
    return (uint32_t)((row >> 3) * 256 + idx * 16);
}

// ---------------------------------------------------------------------------
// Kernel 0a: convert enc fp32 -> fp16, 16 elems/thread
// ---------------------------------------------------------------------------
__global__ __launch_bounds__(256)
void k_convA(const float* __restrict__ A)
{
    size_t i = ((size_t)blockIdx.x * 256 + threadIdx.x) * 16;
    float4 v0 = *(const float4*)(A + i);
    float4 v1 = *(const float4*)(A + i + 4);
    float4 v2 = *(const float4*)(A + i + 8);
    float4 v3 = *(const float4*)(A + i + 12);
    __half2 h0 = __floats2half2_rn(v0.x, v0.y);
    __half2 h1 = __floats2half2_rn(v0.z, v0.w);
    __half2 h2 = __floats2half2_rn(v1.x, v1.y);
    __half2 h3 = __floats2half2_rn(v1.z, v1.w);
    __half2 h4 = __floats2half2_rn(v2.x, v2.y);
    __half2 h5 = __floats2half2_rn(v2.z, v2.w);
    __half2 h6 = __floats2half2_rn(v3.x, v3.y);
    __half2 h7 = __floats2half2_rn(v3.z, v3.w);
    uint4 o0, o1;
    o0.x = *(const uint32_t*)&h0; o0.y = *(const uint32_t*)&h1;
    o0.z = *(const uint32_t*)&h2; o0.w = *(const uint32_t*)&h3;
    o1.x = *(const uint32_t*)&h4; o1.y = *(const uint32_t*)&h5;
    o1.z = *(const uint32_t*)&h6; o1.w = *(const uint32_t*)&h7;
    *(uint4*)(g_Ah + i)     = o0;
    *(uint4*)(g_Ah + i + 8) = o1;
}

// ---------------------------------------------------------------------------
// Kernel 0b: transpose Wh [K,N] fp32 -> g_Bh [N,K] fp16
// ---------------------------------------------------------------------------
__global__ __launch_bounds__(256)
void k_convB(const float* __restrict__ Wh)
{
    __shared__ float tile[32][33];
    const int k0 = blockIdx.y * 32, n0 = blockIdx.x * 32;
    const int tx = threadIdx.x, ty = threadIdx.y;   // 32 x 8
#pragma unroll
    for (int r = 0; r < 4; r++)
        tile[ty + r * 8][tx] = Wh[(size_t)(k0 + ty + r * 8) * U_ + n0 + tx];
    __syncthreads();
#pragma unroll
    for (int r = 0; r < 4; r++) {
        int n = n0 + ty + r * 8;
        int k = k0 + tx;
        g_Bh[(size_t)n * H_ + k] = __float2half(tile[tx][ty + r * 8]);
    }
}

// ---------------------------------------------------------------------------
// Kernel 1: fp16 GEMM (R14 config) + smem-preloaded bh/Wv epilogue
// ---------------------------------------------------------------------------
__global__ __launch_bounds__(256, 2)
void k_gemm_mma(const float* __restrict__ bh, const float* __restrict__ Wv)
{
    extern __shared__ char smem[];
    __shared__ float bh_s[BN];
    __shared__ float wv_s[BN];
    const uint32_t sb = smem_u32(smem);

    const int tid  = threadIdx.x;
    const int warp = tid >> 5;
    const int lane = tid & 31;
    const int g    = lane >> 2;
    const int tig  = lane & 3;
    const int warpM = warp >> 1;
    const int warpN = warp & 1;

    const int rowBase = blockIdx.y * BM;
    const int colBase = blockIdx.x * BN;

    const int lrow = tid >> 1;
    const int lc   = tid & 1;
    const size_t gRowA = (size_t)(rowBase + lrow) * H_ + lc * 8;
    const size_t gRowB = (size_t)(colBase + lrow) * H_ + lc * 8;
    const uint32_t sOff = tile_off(lrow, lc);

#define LOAD_STAGE(KT, BUF)                                                    \
    do {                                                                       \
        const uint32_t sbase_ = sb + (BUF) * STAGEB + sOff;                    \
        const size_t kk_ = (size_t)(KT) * KSTEP;                               \
        cp16(sbase_ + 0 * TILEB, g_Ah + gRowA + kk_);                          \
        cp16(sbase_ + 1 * TILEB, g_Bh + gRowB + kk_);                          \
        cp_commit();                                                           \
    } while (0)

    const int sub = lane >> 3, q = lane & 7;
    uint32_t aOff[2];
#pragma unroll
    for (int mi = 0; mi < 2; mi++) {
        const int rowA = warpM * 32 + mi * 16 + ((sub & 1) ? 8 : 0) + q;
        aOff[mi] = tile_off(rowA, sub >> 1);
    }
    uint32_t bOff[4];
#pragma unroll
    for (int nip = 0; nip < 4; nip++) {
        const int rowB = warpN * 64 + nip * 16 + ((sub & 2) ? 8 : 0) + q;
        bOff[nip] = tile_off(rowB, sub & 1);
    }

    float d[2][8][4];
#pragma unroll
    for (int mi = 0; mi < 2; mi++)
#pragma unroll
        for (int ni = 0; ni < 8; ni++)
#pragma unroll
            for (int qq = 0; qq < 4; qq++) d[mi][ni][qq] = 0.0f;

    // preload epilogue coefficients (overlapped with pipeline fill)
    if (tid < BN) {
        bh_s[tid] = __ldg(bh + colBase + tid);
        wv_s[tid] = __ldg(Wv + colBase + tid);
    }

    LOAD_STAGE(0, 0);
    LOAD_STAGE(1, 1);
    LOAD_STAGE(2, 2);

#pragma unroll 4
    for (int kt = 0; kt < NK; kt++) {
        cp_wait<2>();
        __syncthreads();
        if (kt + 3 < NK) LOAD_STAGE(kt + 3, (kt + 3) & (PIPE - 1));
        else cp_commit();

        const uint32_t stage = sb + (uint32_t)(kt & (PIPE - 1)) * STAGEB;
        const uint32_t Ah_s = stage, Bh_s = stage + TILEB;

        uint32_t ah[2][4];
        ldsm4(ah[0], Ah_s + aOff[0]);
        ldsm4(ah[1], Ah_s + aOff[1]);

#pragma unroll
        for (int nip = 0; nip < 4; nip++) {
            uint32_t b4[4];
            ldsm4(b4, Bh_s + bOff[nip]);
            const int n0 = nip * 2, n1 = n0 + 1;
            mma16816(d[0][n0], ah[0], b4[0], b4[1]);
            mma16816(d[1][n0], ah[1], b4[0], b4[1]);
            mma16816(d[0][n1], ah[0], b4[2], b4[3]);
            mma16816(d[1][n1], ah[1], b4[2], b4[3]);
        }
    }
    __syncthreads();

    // fused epilogue: s = sum_n tanh(C + bh)*Wv (coeffs from smem, broadcast)
    float s[2][2] = {{0.f, 0.f}, {0.f, 0.f}};
#pragma unroll
    for (int ni = 0; ni < 8; ni++) {
        const int n0 = warpN * 64 + ni * 8 + 2 * tig;
        const float bb0 = bh_s[n0], bb1 = bh_s[n0 + 1];
        const float w0  = wv_s[n0], w1  = wv_s[n0 + 1];
#pragma unroll
        for (int mi = 0; mi < 2; mi++) {
            s[mi][0] = fmaf(tanh_fast(d[mi][ni][0] + bb0), w0, s[mi][0]);
            s[mi][0] = fmaf(tanh_fast(d[mi][ni][1] + bb1), w1, s[mi][0]);
            s[mi][1] = fmaf(tanh_fast(d[mi][ni][2] + bb0), w0, s[mi][1]);
            s[mi][1] = fmaf(tanh_fast(d[mi][ni][3] + bb1), w1, s[mi][1]);
        }
    }
#pragma unroll
    for (int off = 1; off <= 2; off <<= 1) {
#pragma unroll
        for (int mi = 0; mi < 2; mi++) {
            s[mi][0] += __shfl_xor_sync(0xFFFFFFFFu, s[mi][0], off);
            s[mi][1] += __shfl_xor_sync(0xFFFFFFFFu, s[mi][1], off);
        }
    }
    float* red = (float*)smem;
    if (tig == 0) {
#pragma unroll
        for (int mi = 0; mi < 2; mi++) {
            red[(warpM * 32 + mi * 16 + g) * 2 + warpN]     = s[mi][0];
            red[(warpM * 32 + mi * 16 + 8 + g) * 2 + warpN] = s[mi][1];
        }
    }
    __syncthreads();
    if (tid < BM)
        g_partial[(size_t)(rowBase + tid) * NBLK + blockIdx.x] = red[tid * 2] + red[tid * 2 + 1];
#undef LOAD_STAGE
}

// ---------------------------------------------------------------------------
// Kernel 2: fused softmax + context partial (reads fp16 g_Ah), TCH=16
// ---------------------------------------------------------------------------
__global__ __launch_bounds__(256)
void k_ctx_fused(float* __restrict__ attn_out)
{
    const int tc  = blockIdx.x;
    const int b   = blockIdx.y;
    const int tid = threadIdx.x;

    __shared__ float w[T_];
    __shared__ float rbuf[8];

    const float* p0 = g_partial + ((size_t)b * T_ + tid) * NBLK;
    const float* p1 = g_partial + ((size_t)b * T_ + tid + 256) * NBLK;
    float s0 = 0.f, s1 = 0.f;
#pragma unroll
    for (int i = 0; i < NBLK; i++) { s0 += p0[i]; s1 += p1[i]; }

    float mx = fmaxf(s0, s1);
#pragma unroll
    for (int o = 16; o > 0; o >>= 1) mx = fmaxf(mx, __shfl_xor_sync(0xFFFFFFFFu, mx, o));
    if ((tid & 31) == 0) rbuf[tid >> 5] = mx;
    __syncthreads();
    mx = rbuf[0];
#pragma unroll
    for (int i = 1; i < 8; i++) mx = fmaxf(mx, rbuf[i]);
    __syncthreads();

    const float e0 = expf(s0 - mx);
    const float e1 = expf(s1 - mx);

    float sm = e0 + e1;
#pragma unroll
    for (int o = 16; o > 0; o >>= 1) sm += __shfl_xor_sync(0xFFFFFFFFu, sm, o);
    if ((tid & 31) == 0) rbuf[tid >> 5] = sm;
    __syncthreads();
    sm = rbuf[0];
#pragma unroll
    for (int i = 1; i < 8; i++) sm += rbuf[i];

    const float inv = __fdividef(1.0f, sm);
    w[tid]       = e0 * inv;
    w[tid + 256] = e1 * inv;
    if (tc == 0) {
        attn_out[b * T_ + tid]       = e0 * inv;
        attn_out[b * T_ + tid + 256] = e1 * inv;
    }
    __syncthreads();

    const int h0 = tid * 4;
    const __half* base = g_Ah + ((size_t)b * T_ + tc * TSEG) * H_ + h0;
    float a0 = 0.f, a1 = 0.f, a2 = 0.f, a3 = 0.f;
#pragma unroll 8
    for (int t = 0; t < TSEG; t++) {
        const float wt = w[tc * TSEG + t];
        const uint2 v = *(const uint2*)(base + (size_t)t * H_);
        const __half2 q0 = *(const __half2*)&v.x;
        const __half2 q1 = *(const __half2*)&v.y;
        const float2 f0 = __half22float2(q0);
        const float2 f1 = __half22float2(q1);
        a0 = fmaf(wt, f0.x, a0);
        a1 = fmaf(wt, f0.y, a1);
        a2 = fmaf(wt, f1.x, a2);
        a3 = fmaf(wt, f1.y, a3);
    }
    float4 r = make_float4(a0, a1, a2, a3);
    *(float4*)(g_ctxp + (size_t)(b * TCH + tc) * H_ + h0) = r;
}

// ---------------------------------------------------------------------------
// Kernel 3: reduce context partials, float4 per thread
// ---------------------------------------------------------------------------
__global__ __launch_bounds__(256)
void k_ctx_reduce(float* __restrict__ ctx)
{
    const int i4 = blockIdx.x * 256 + threadIdx.x;   // over B_*H_/4
    const int b  = (i4 * 4) >> 10;
    const int h  = (i4 * 4) & (H_ - 1);
    float4 s = make_float4(0.f, 0.f, 0.f, 0.f);
#pragma unroll
    for (int p = 0; p < TCH; p++) {
        const float4 v = *(const float4*)(g_ctxp + (size_t)(b * TCH + p) * H_ + h);
        s.x += v.x; s.y += v.y; s.z += v.z; s.w += v.w;
    }
    ((float4*)ctx)[i4] = s;
}

// ---------------------------------------------------------------------------
// Launch. Inputs: dec_hidden, enc_output, Wh, bh, Ws, bs, Wv, bv.
// dec/Ws/bs/bv cancel inside softmax. Output: [ctx (64*1024) | attn (64*512)].
// ---------------------------------------------------------------------------
extern "C" void kernel_launch(void* const* d_in, const int* in_sizes, int n_in,
                              void* d_out, int out_size)
{
    (void)in_sizes; (void)n_in; (void)out_size;
    const float* enc = (const float*)d_in[1];
    const float* Wh  = (const float*)d_in[2];
    const float* bh  = (const float*)d_in[3];
    const float* Wv  = (const float*)d_in[6];

    float* out  = (float*)d_out;
    float* ctx  = out;
    float* attn = out + B_ * H_;

    static bool attr_done = false;
    if (!attr_done) {
        cudaFuncSetAttribute(k_gemm_mma, cudaFuncAttributeMaxDynamicSharedMemorySize, SMEM_TOTAL);
        attr_done = true;
    }

    k_convA<<<(M_ * H_) / (256 * 16), 256>>>(enc);
    k_convB<<<dim3(U_ / 32, H_ / 32), dim3(32, 8)>>>(Wh);
    k_gemm_mma<<<dim3(NBLK, M_ / BM), 256, SMEM_TOTAL>>>(bh, Wv);
    k_ctx_fused<<<dim3(TCH, B_), 256>>>(attn);
    k_ctx_reduce<<<(B_ * H_) / (256 * 4), 256>>>(ctx);
}